// round 4
// baseline (speedup 1.0000x reference)
#include <cuda_runtime.h>
#include <math.h>

#define Bx 32
#define Dd 256
#define Kk 2048
#define Nn 32768
#define HWp 1024

#define TM 64
#define TN 128
#define TK 8
#define XS_STRIDE 68   // 64 + 4 pad (68*4=272 bytes, %16==0 keeps float4 alignment)

#define Q_ELEMS   8388608
#define FULL_OUT  8421379

// ---- device scratch (no allocations allowed) ----
__device__ float g_En[Dd * Kk];     // normalized embedding, 2 MB
__device__ float g_inv[Kk];
__device__ int   g_idx[Nn];
__device__ int   g_hist[Kk];
__device__ float g_part[128];

// ---------------------------------------------------------------------------
// Kernel 1: per-column inverse norms of embedding table + zero histogram
// ---------------------------------------------------------------------------
__global__ void k_invnorm(const float* __restrict__ E) {
    int k = blockIdx.x * blockDim.x + threadIdx.x;   // 0..2047, coalesced over k
    float ss = 0.f;
#pragma unroll 8
    for (int d = 0; d < Dd; ++d) {
        float v = E[d * Kk + k];
        ss = fmaf(v, v, ss);
    }
    g_inv[k] = 1.0f / fmaxf(sqrtf(ss), 1e-12f);
    g_hist[k] = 0;
}

// ---------------------------------------------------------------------------
// Kernel 2: normalized embedding table En = E * inv_norm[col]
// ---------------------------------------------------------------------------
__global__ void k_norm(const float* __restrict__ E) {
    int i = blockIdx.x * blockDim.x + threadIdx.x;   // 524288 elems
    g_En[i] = E[i] * g_inv[i & (Kk - 1)];
}

// ---------------------------------------------------------------------------
// Kernel 3: fused fp32 GEMM + running argmax over codebook columns.
// A-matrix rows are spatial positions n = b*1024 + hw; feature d lives at
// x[b*D*HW + d*HW + hw]  (channels-first!). For a tile of 64 consecutive n
// (same b; 64 | 1024 so tiles never straddle b), the 64 rows at fixed d are
// 64 CONTIGUOUS floats -> transposed smem tile loads as straight float4 copies.
// Block: 256 threads (tx 16 x ty 16), tile TM=64 x TN=128, micro 4x8.
// ---------------------------------------------------------------------------
__global__ __launch_bounds__(256, 3) void k_gemm_argmax(const float* __restrict__ x) {
    extern __shared__ float sm[];
    float* Xs = sm;                       // [256][XS_STRIDE]
    float* Es = sm + Dd * XS_STRIDE;      // [TK][TN]

    const int tid = threadIdx.x;
    const int tx = tid & 15;
    const int ty = tid >> 4;
    const int rbase = blockIdx.x * TM;    // global n of tile row 0
    const int b  = rbase >> 10;
    const int hw = rbase & 1023;

    // Load X tile: Xs[d][0..63] = x[b*D*HW + d*HW + hw + 0..63]
    const float* xb = x + (size_t)b * Dd * HWp + hw;
#pragma unroll
    for (int p = 0; p < 16; ++p) {
        int idx = p * 256 + tid;          // 0..4095
        int d  = idx >> 4;                // 0..255
        int r4 = idx & 15;                // float4 index along the 64 rows
        float4 v = *(const float4*)&xb[(size_t)d * HWp + r4 * 4];
        *(float4*)&Xs[d * XS_STRIDE + r4 * 4] = v;
    }

    float bestv[4];
    int   besti[4];
#pragma unroll
    for (int i = 0; i < 4; ++i) { bestv[i] = -3.0e38f; besti[i] = 0; }

    const int edr = tid >> 5;   // 0..7   (row of Es to fill)
    const int ec4 = tid & 31;   // 0..31  (float4 col of Es)

    for (int ct = 0; ct < Kk / TN; ++ct) {
        const int cbase = ct * TN;
        float acc[32];
#pragma unroll
        for (int q = 0; q < 32; ++q) acc[q] = 0.f;

        for (int ds = 0; ds < Dd / TK; ++ds) {
            const int dbase = ds * TK;
            __syncthreads();   // protect Es from previous stage readers (covers Xs on iter 0)
            ((float4*)Es)[edr * (TN / 4) + ec4] =
                *(const float4*)&g_En[(dbase + edr) * Kk + cbase + ec4 * 4];
            __syncthreads();

#pragma unroll
            for (int dk = 0; dk < TK; ++dk) {
                float4 a  = *(const float4*)&Xs[(dbase + dk) * XS_STRIDE + ty * 4];
                // split halves at +0 and +64: 16-byte lane stride -> conflict-free LDS.128
                float4 b0 = *(const float4*)&Es[dk * TN + tx * 4];
                float4 b1 = *(const float4*)&Es[dk * TN + 64 + tx * 4];
                float av[4] = {a.x, a.y, a.z, a.w};
                float bv[8] = {b0.x, b0.y, b0.z, b0.w, b1.x, b1.y, b1.z, b1.w};
#pragma unroll
                for (int i = 0; i < 4; ++i)
#pragma unroll
                    for (int j = 0; j < 8; ++j)
                        acc[i * 8 + j] = fmaf(av[i], bv[j], acc[i * 8 + j]);
            }
        }

        // running per-row argmax over this thread's 8 columns
        // column of acc[i][j]: j<4 -> cbase + tx*4 + j ; j>=4 -> cbase + 64 + tx*4 + (j-4)
#pragma unroll
        for (int i = 0; i < 4; ++i) {
#pragma unroll
            for (int j = 0; j < 8; ++j) {
                float v = acc[i * 8 + j];
                int col = cbase + ((j < 4) ? (tx * 4 + j) : (64 + tx * 4 + (j - 4)));
                if (v > bestv[i] || (v == bestv[i] && col < besti[i])) {
                    bestv[i] = v;
                    besti[i] = col;
                }
            }
        }
    }

    // reduce across the 16 tx lanes (tx bits are the low 4 lane bits)
#pragma unroll
    for (int i = 0; i < 4; ++i) {
        float v = bestv[i];
        int   bi = besti[i];
#pragma unroll
        for (int m = 1; m < 16; m <<= 1) {
            float ov = __shfl_xor_sync(0xffffffffu, v, m);
            int   oi = __shfl_xor_sync(0xffffffffu, bi, m);
            if (ov > v || (ov == v && oi < bi)) { v = ov; bi = oi; }
        }
        if (tx == 0) g_idx[rbase + ty * 4 + i] = bi;
    }
}

// ---------------------------------------------------------------------------
// Kernel 4: gather quantized vectors (unnormalized table), fused MSE partials,
// histogram, and index output. One thread per spatial position n.
// ---------------------------------------------------------------------------
__global__ void k_gather(const float* __restrict__ x, const float* __restrict__ E,
                         float* __restrict__ out, int extras) {
    __shared__ float red[256];
    const int tid = threadIdx.x;
    const int n = blockIdx.x * 256 + tid;
    const int idx = g_idx[n];
    const int b = n >> 10;
    const int hw = n & 1023;

    const float* xb = x + (size_t)b * Dd * HWp + hw;
    float* ob = out + (size_t)b * Dd * HWp + hw;

    float acc = 0.f;
#pragma unroll 4
    for (int d = 0; d < Dd; ++d) {
        float q  = E[d * Kk + idx];   // L2-resident gather (table = 2 MB)
        float xv = xb[(size_t)d * HWp];
        ob[(size_t)d * HWp] = q;      // coalesced: consecutive n -> consecutive hw
        float df = xv - q;
        acc = fmaf(df, df, acc);
    }
    atomicAdd(&g_hist[idx], 1);
    if (extras) out[Q_ELEMS + 3 + n] = (float)idx;

    red[tid] = acc;
    __syncthreads();
    for (int s = 128; s > 0; s >>= 1) {
        if (tid < s) red[tid] += red[tid + s];
        __syncthreads();
    }
    if (tid == 0) g_part[blockIdx.x] = red[0];
}

// ---------------------------------------------------------------------------
// Kernel 5: finalize scalars (dict == commit == MSE) and entropy loss.
// ---------------------------------------------------------------------------
__global__ void k_final(float* __restrict__ out, int extras) {
    __shared__ float red[256];
    const int tid = threadIdx.x;

    red[tid] = (tid < 128) ? g_part[tid] : 0.f;
    __syncthreads();
    for (int s = 128; s > 0; s >>= 1) {
        if (tid < s) red[tid] += red[tid + s];
        __syncthreads();
    }
    float mse = red[0] / (float)Q_ELEMS;
    __syncthreads();

    float e = 0.f;
    for (int bin = tid; bin < Kk; bin += 256) {
        float p = (float)g_hist[bin] / (float)Nn;
        e += p * logf(p + 1e-10f);
    }
    red[tid] = e;
    __syncthreads();
    for (int s = 128; s > 0; s >>= 1) {
        if (tid < s) red[tid] += red[tid + s];
        __syncthreads();
    }
    if (tid == 0 && extras) {
        out[Q_ELEMS + 0] = mse;      // dictionary_loss
        out[Q_ELEMS + 1] = mse;      // commitment_loss (same value)
        out[Q_ELEMS + 2] = red[0];   // entropy_loss
    }
}

// ---------------------------------------------------------------------------
extern "C" void kernel_launch(void* const* d_in, const int* in_sizes, int n_in,
                              void* d_out, int out_size) {
    const float* x = (const float*)d_in[0];            // [32,256,32,32]
    const float* E = (const float*)d_in[1];            // [256,2048]
    float* out = (float*)d_out;
    const int extras = (out_size >= FULL_OUT) ? 1 : 0;

    k_invnorm<<<Kk / 256, 256>>>(E);
    k_norm<<<(Dd * Kk) / 256, 256>>>(E);

    const int smem = (Dd * XS_STRIDE + TK * TN) * (int)sizeof(float);  // 73728 B
    cudaFuncSetAttribute(k_gemm_argmax,
                         cudaFuncAttributeMaxDynamicSharedMemorySize, smem);
    k_gemm_argmax<<<Nn / TM, 256, smem>>>(x);

    k_gather<<<Nn / 256, 256>>>(x, E, out, extras);
    k_final<<<1, 256>>>(out, extras);
}

// round 7
// speedup vs baseline: 1.5199x; 1.5199x over previous
#include <cuda_runtime.h>
#include <cuda_bf16.h>
#include <cstdint>
#include <math.h>

#define Bx 32
#define Dd 256
#define Kk 2048
#define Nn 32768
#define HWp 1024

#define Q_ELEMS   8388608
#define FULL_OUT  8421379
#define TAU       4e-4f

// ---- device scratch (no dynamic allocations allowed) ----
__device__ __nv_bfloat16 g_Xhi[Nn * Dd];    // 16.8 MB [N][D]
__device__ __nv_bfloat16 g_Xlo[Nn * Dd];    // 16.8 MB
__device__ __nv_bfloat16 g_BhiT[Dd * Kk];   // 1 MB   [D][K]  (normalized, hi)
__device__ __nv_bfloat16 g_BloT[Dd * Kk];   // 1 MB
__device__ float g_Ef[Kk * Dd];             // 2 MB   [K][D] normalized fp32 (rescue)
__device__ float g_inv[Kk];
__device__ int   g_idx[Nn];
__device__ int   g_hist[Kk];
__device__ float g_part[512];
__device__ int   g_rcnt;
__device__ int   g_rlist[Nn];

// ======================= warp-MMA helpers (compute_80+ PTX) ================
__device__ __forceinline__ uint32_t smem_u32(const void* p) {
    uint32_t a;
    asm("{ .reg .u64 t; cvta.to.shared.u64 t, %1; cvt.u32.u64 %0, t; }" : "=r"(a) : "l"(p));
    return a;
}
__device__ __forceinline__ void ldsm_x4(uint32_t* r, uint32_t addr) {
    asm volatile("ldmatrix.sync.aligned.m8n8.x4.shared.b16 {%0,%1,%2,%3}, [%4];"
        : "=r"(r[0]), "=r"(r[1]), "=r"(r[2]), "=r"(r[3]) : "r"(addr));
}
__device__ __forceinline__ void ldsm_x4_t(uint32_t* r, uint32_t addr) {
    asm volatile("ldmatrix.sync.aligned.m8n8.x4.trans.shared.b16 {%0,%1,%2,%3}, [%4];"
        : "=r"(r[0]), "=r"(r[1]), "=r"(r[2]), "=r"(r[3]) : "r"(addr));
}
__device__ __forceinline__ void mma_bf16(float* c, const uint32_t* a, const uint32_t* b) {
    asm("mma.sync.aligned.m16n8k16.row.col.f32.bf16.bf16.f32 "
        "{%0,%1,%2,%3}, {%4,%5,%6,%7}, {%8,%9}, {%0,%1,%2,%3};"
        : "+f"(c[0]), "+f"(c[1]), "+f"(c[2]), "+f"(c[3])
        : "r"(a[0]), "r"(a[1]), "r"(a[2]), "r"(a[3]), "r"(b[0]), "r"(b[1]));
}

// ---------------------------------------------------------------------------
// Kernel 1: per-column inverse norms + zero histogram + reset rescue count
// ---------------------------------------------------------------------------
__global__ void k_invnorm(const float* __restrict__ E) {
    int k = blockIdx.x * blockDim.x + threadIdx.x;
    float ss = 0.f;
#pragma unroll 8
    for (int d = 0; d < Dd; ++d) { float v = E[d * Kk + k]; ss = fmaf(v, v, ss); }
    g_inv[k] = 1.0f / fmaxf(sqrtf(ss), 1e-12f);
    g_hist[k] = 0;
    if (k == 0) g_rcnt = 0;
}

// ---------------------------------------------------------------------------
// Kernel 2: transpose+split X: [B,D,H,W] fp32 -> Xhi/Xlo [N,D] bf16 row-major
// ---------------------------------------------------------------------------
__global__ __launch_bounds__(256) void k_prepx(const float* __restrict__ x) {
    __shared__ float t[64][65];
    const int tid = threadIdx.x;
    const int hw0 = blockIdx.x * 64, d0 = blockIdx.y * 64, b = blockIdx.z;
    const float* xb = x + ((size_t)b * Dd + d0) * HWp + hw0;
#pragma unroll
    for (int i = 0; i < 16; ++i) {
        int idx = i * 256 + tid, di = idx >> 6, hwi = idx & 63;
        t[di][hwi] = xb[(size_t)di * HWp + hwi];
    }
    __syncthreads();
    const int n0 = b * HWp + hw0;
#pragma unroll
    for (int i = 0; i < 16; ++i) {
        int idx = i * 256 + tid, hwi = idx >> 6, di = idx & 63;
        float v = t[di][hwi];
        __nv_bfloat16 h = __float2bfloat16(v);
        float lo = v - __bfloat162float(h);
        size_t o = (size_t)(n0 + hwi) * Dd + d0 + di;
        g_Xhi[o] = h;
        g_Xlo[o] = __float2bfloat16(lo);
    }
}

// ---------------------------------------------------------------------------
// Kernel 3: codebook prep: E [D,K] -> g_Ef [K][D] fp32 normalized,
//           g_BhiT/g_BloT [D][K] bf16 split (for MMA B chunks, d-major rows)
// ---------------------------------------------------------------------------
__global__ __launch_bounds__(256) void k_prepe(const float* __restrict__ E) {
    __shared__ float t[64][65];
    const int tid = threadIdx.x;
    const int k0 = blockIdx.x * 64, d0 = blockIdx.y * 64;
#pragma unroll
    for (int i = 0; i < 16; ++i) {
        int idx = i * 256 + tid, di = idx >> 6, ki = idx & 63;
        t[di][ki] = E[(size_t)(d0 + di) * Kk + k0 + ki] * g_inv[k0 + ki];
    }
    __syncthreads();
    // [K][D] fp32 (rescue table)
#pragma unroll
    for (int i = 0; i < 16; ++i) {
        int idx = i * 256 + tid, ki = idx >> 6, di = idx & 63;
        g_Ef[(size_t)(k0 + ki) * Dd + d0 + di] = t[di][ki];
    }
    // [D][K] bf16 hi/lo (MMA B)
#pragma unroll
    for (int i = 0; i < 16; ++i) {
        int idx = i * 256 + tid, di = idx >> 6, ki = idx & 63;
        float v = t[di][ki];
        __nv_bfloat16 h = __float2bfloat16(v);
        float lo = v - __bfloat162float(h);
        size_t o = (size_t)(d0 + di) * Kk + k0 + ki;
        g_BhiT[o] = h;
        g_BloT[o] = __float2bfloat16(lo);
    }
}

// ---------------------------------------------------------------------------
// Kernel 4: warp-MMA split-3 bf16 GEMM + top-2 argmax.
// CTA: 256 thr (8 warps: wm=wid&3 -> 32 rows, wn=wid>>2 -> 64 cols), 128 rows.
// A (hi+lo) resident in SMEM, XOR-swizzled; B streamed as [k16][n128] chunks
// from g_B*T, double-buffered. Per-thread running top-2 over its columns.
// ---------------------------------------------------------------------------
#define SM_ALO 65536
#define SM_B   131072
#define SM_RED 147456
#define SM_TOT 150528

__global__ __launch_bounds__(256, 1) void k_mma_argmax() {
    extern __shared__ char sm[];
    const uint32_t sb = smem_u32(sm);
    const int tid = threadIdx.x;
    const int lane = tid & 31;
    const int wid = tid >> 5;
    const int wm = wid & 3, wn = wid >> 2;
    const int rbase = blockIdx.x * 128;

    // ---- load A (both splits) into swizzled SMEM ----
#pragma unroll
    for (int s = 0; s < 2; ++s) {
        const __nv_bfloat16* src = s ? g_Xlo : g_Xhi;
#pragma unroll
        for (int i = 0; i < 16; ++i) {
            int idx = i * 256 + tid;
            int r = idx >> 5, u = idx & 31;
            uint4 v = *(const uint4*)(src + (size_t)(rbase + r) * Dd + u * 8);
            *(uint4*)(sm + s * SM_ALO + r * 512 + ((u ^ (r & 7)) << 4)) = v;
        }
    }
    // ---- preload B chunk 0 into stage 0 ----
    {
        size_t so = (size_t)(tid >> 4) * (Kk * 2) + (size_t)(tid & 15) * 16;
        uint4 vh = *(const uint4*)((const char*)g_BhiT + so);
        uint4 vl = *(const uint4*)((const char*)g_BloT + so);
        uint32_t dst = SM_B + (tid >> 4) * 256 + (((tid & 15) ^ ((tid >> 4) & 7)) << 4);
        *(uint4*)(sm + dst) = vh;
        *(uint4*)(sm + dst + 4096) = vl;
    }
    __syncthreads();

    float c[2][8][4];
#pragma unroll
    for (int mi = 0; mi < 2; ++mi)
#pragma unroll
        for (int p = 0; p < 8; ++p)
#pragma unroll
            for (int q = 0; q < 4; ++q) c[mi][p][q] = 0.f;

    float v1[4], v2[4];
    int   i1[4];
#pragma unroll
    for (int s = 0; s < 4; ++s) { v1[s] = -3.0e38f; v2[s] = -3.0e38f; i1[s] = 0; }

    int stage = 0;
    uint4 nxh, nxl;
    const int ldrow = tid >> 4, ldu = tid & 15;

    for (int cid = 0; cid < 256; ++cid) {
        const int ct = cid >> 4, kc = cid & 15;

        // prefetch next chunk (LDG only; STS after MMA)
        if (cid < 255) {
            int nkc = (cid + 1) & 15, ncb = ((cid + 1) >> 4) << 7;
            size_t so = (size_t)(nkc * 16 + ldrow) * (Kk * 2) + (size_t)ncb * 2 + (size_t)ldu * 16;
            nxh = *(const uint4*)((const char*)g_BhiT + so);
            nxl = *(const uint4*)((const char*)g_BloT + so);
        }

        // ---- fragments ----
        uint32_t ah[2][4], al[2][4];
#pragma unroll
        for (int mi = 0; mi < 2; ++mi) {
            int r0 = wm * 32 + mi * 16 + (lane & 15);
            int u0 = kc * 2 + (lane >> 4);
            uint32_t aaddr = sb + r0 * 512 + ((u0 ^ (r0 & 7)) << 4);
            ldsm_x4(ah[mi], aaddr);
            ldsm_x4(al[mi], aaddr + SM_ALO);
        }
        uint32_t bh4[4][4], bl4[4][4];
        const uint32_t bbase = sb + SM_B + stage * 8192;
        const int kk = (lane & 7) + ((lane >> 3) & 1) * 8;
#pragma unroll
        for (int p = 0; p < 4; ++p) {
            int u0 = wn * 8 + p * 2 + (lane >> 4);
            uint32_t baddr = bbase + kk * 256 + ((u0 ^ (kk & 7)) << 4);
            ldsm_x4_t(bh4[p], baddr);
            ldsm_x4_t(bl4[p], baddr + 4096);
        }
        // ---- 48 HMMA: hi*hi + hi*lo + lo*hi ----
#pragma unroll
        for (int mi = 0; mi < 2; ++mi)
#pragma unroll
            for (int p = 0; p < 4; ++p) {
                mma_bf16(c[mi][2 * p],     ah[mi], &bh4[p][0]);
                mma_bf16(c[mi][2 * p + 1], ah[mi], &bh4[p][2]);
                mma_bf16(c[mi][2 * p],     ah[mi], &bl4[p][0]);
                mma_bf16(c[mi][2 * p + 1], ah[mi], &bl4[p][2]);
                mma_bf16(c[mi][2 * p],     al[mi], &bh4[p][0]);
                mma_bf16(c[mi][2 * p + 1], al[mi], &bh4[p][2]);
            }

        // store prefetched chunk into other stage
        if (cid < 255) {
            uint32_t dst = SM_B + (stage ^ 1) * 8192 + ldrow * 256 + ((ldu ^ (ldrow & 7)) << 4);
            *(uint4*)(sm + dst) = nxh;
            *(uint4*)(sm + dst + 4096) = nxl;
        }
        __syncthreads();
        stage ^= 1;

        // ---- ctile epilogue: fold accumulators into running top-2 ----
        if (kc == 15) {
            const int cb = ct * 128 + wn * 64 + (lane & 3) * 2;
#pragma unroll
            for (int mi = 0; mi < 2; ++mi)
#pragma unroll
                for (int p = 0; p < 8; ++p)
#pragma unroll
                    for (int q = 0; q < 4; ++q) {
                        float v = c[mi][p][q];
                        int col = cb + p * 8 + (q & 1);
                        int slot = mi * 2 + (q >> 1);
                        if (v > v1[slot]) { v2[slot] = v1[slot]; v1[slot] = v; i1[slot] = col; }
                        else if (v > v2[slot]) { v2[slot] = v; }
                        c[mi][p][q] = 0.f;
                    }
        }
    }

    // ---- cross-lane merge over the 4 lanes sharing a row ----
#pragma unroll
    for (int s = 0; s < 4; ++s) {
#pragma unroll
        for (int m = 1; m <= 2; m <<= 1) {
            float ov1 = __shfl_xor_sync(0xffffffffu, v1[s], m);
            float ov2 = __shfl_xor_sync(0xffffffffu, v2[s], m);
            int   oi1 = __shfl_xor_sync(0xffffffffu, i1[s], m);
            if (ov1 > v1[s]) { v2[s] = fmaxf(v1[s], ov2); v1[s] = ov1; i1[s] = oi1; }
            else             { v2[s] = fmaxf(v2[s], ov1); }
        }
    }
    float* sv1 = (float*)(sm + SM_RED);
    float* sv2 = (float*)(sm + SM_RED + 1024);
    int*   si1 = (int*)  (sm + SM_RED + 2048);
    if ((lane & 3) == 0) {
#pragma unroll
        for (int s = 0; s < 4; ++s) {
            int row = wm * 32 + (s >> 1) * 16 + (s & 1) * 8 + (lane >> 2);
            sv1[row * 2 + wn] = v1[s];
            sv2[row * 2 + wn] = v2[s];
            si1[row * 2 + wn] = i1[s];
        }
    }
    __syncthreads();
    if (tid < 128) {
        float a1 = sv1[tid * 2], a2 = sv2[tid * 2];
        float b1 = sv1[tid * 2 + 1], b2 = sv2[tid * 2 + 1];
        int ai = si1[tid * 2], bi = si1[tid * 2 + 1];
        float t1, t2; int ti;
        if (b1 > a1) { t1 = b1; ti = bi; t2 = fmaxf(a1, b2); }
        else         { t1 = a1; ti = ai; t2 = fmaxf(b1, a2); }
        g_idx[rbase + tid] = ti;
        if (t1 - t2 < TAU) {
            int p = atomicAdd(&g_rcnt, 1);
            g_rlist[p] = rbase + tid;
        }
    }
}

// ---------------------------------------------------------------------------
// Kernel 5: exact fp32 rescue for rows with small top1-top2 gap.
// Tiles of 8 rows share one streaming pass over the 2 MB fp32 table.
// ---------------------------------------------------------------------------
__global__ __launch_bounds__(256) void k_rescue(const float* __restrict__ x) {
    __shared__ float sx[8][257];
    __shared__ int   srows[8];
    __shared__ float rv[256];
    __shared__ int   ri[256];
    const int tid = threadIdx.x;
    const int total = g_rcnt;

    for (int t0 = blockIdx.x * 8; t0 < total; t0 += gridDim.x * 8) {
        const int m = min(8, total - t0);
        if (tid < 8) srows[tid] = (tid < m) ? g_rlist[t0 + tid] : 0;
        __syncthreads();
        for (int j = 0; j < 8; ++j) {
            int n = srows[j];
            int b = n >> 10, hw = n & 1023;
            sx[j][tid] = (j < m) ? x[((size_t)b * Dd + tid) * HWp + hw] : 0.f;
        }
        __syncthreads();

        float bv[8]; int bi[8];
#pragma unroll
        for (int j = 0; j < 8; ++j) { bv[j] = -3.0e38f; bi[j] = 0; }
        for (int s = 0; s < 8; ++s) {
            int k = s * 256 + tid;
            const float* er = g_Ef + (size_t)k * Dd;
            float dot[8];
#pragma unroll
            for (int j = 0; j < 8; ++j) dot[j] = 0.f;
            for (int d = 0; d < Dd; d += 4) {
                float4 e = *(const float4*)(er + d);
#pragma unroll
                for (int j = 0; j < 8; ++j) {
                    dot[j] = fmaf(sx[j][d], e.x, dot[j]);
                    dot[j] = fmaf(sx[j][d + 1], e.y, dot[j]);
                    dot[j] = fmaf(sx[j][d + 2], e.z, dot[j]);
                    dot[j] = fmaf(sx[j][d + 3], e.w, dot[j]);
                }
            }
#pragma unroll
            for (int j = 0; j < 8; ++j)
                if (dot[j] > bv[j]) { bv[j] = dot[j]; bi[j] = k; }
        }
        for (int j = 0; j < 8; ++j) {
            rv[tid] = bv[j]; ri[tid] = bi[j];
            __syncthreads();
            for (int s2 = 128; s2 > 0; s2 >>= 1) {
                if (tid < s2) {
                    if (rv[tid + s2] > rv[tid] ||
                        (rv[tid + s2] == rv[tid] && ri[tid + s2] < ri[tid])) {
                        rv[tid] = rv[tid + s2]; ri[tid] = ri[tid + s2];
                    }
                }
                __syncthreads();
            }
            if (tid == 0 && j < m) g_idx[srows[j]] = ri[0];
            __syncthreads();
        }
    }
}

// ---------------------------------------------------------------------------
// Kernel 6: gather + fused MSE partials + histogram + index output.
// Split along D (blockIdx.y = quarter) for 4x occupancy.
// ---------------------------------------------------------------------------
__global__ void k_gather(const float* __restrict__ x, const float* __restrict__ E,
                         float* __restrict__ out, int extras) {
    __shared__ float red[256];
    const int tid = threadIdx.x;
    const int n = blockIdx.x * 256 + tid;
    const int q = blockIdx.y;
    const int d0 = q * 64;
    const int idx = g_idx[n];
    const int b = n >> 10;
    const int hw = n & 1023;

    const float* xb = x + ((size_t)b * Dd + d0) * HWp + hw;
    float* ob = out + ((size_t)b * Dd + d0) * HWp + hw;

    float acc = 0.f;
#pragma unroll 4
    for (int d = 0; d < 64; ++d) {
        float qv = E[(d0 + d) * Kk + idx];
        float xv = xb[(size_t)d * HWp];
        ob[(size_t)d * HWp] = qv;
        float df = xv - qv;
        acc = fmaf(df, df, acc);
    }
    if (q == 0) {
        atomicAdd(&g_hist[idx], 1);
        if (extras) out[Q_ELEMS + 3 + n] = (float)idx;
    }

    red[tid] = acc;
    __syncthreads();
    for (int s = 128; s > 0; s >>= 1) {
        if (tid < s) red[tid] += red[tid + s];
        __syncthreads();
    }
    if (tid == 0) g_part[blockIdx.x * 4 + q] = red[0];
}

// ---------------------------------------------------------------------------
// Kernel 7: finalize scalars
// ---------------------------------------------------------------------------
__global__ void k_final(float* __restrict__ out, int extras) {
    __shared__ float red[256];
    const int tid = threadIdx.x;

    red[tid] = g_part[tid] + g_part[tid + 256];
    __syncthreads();
    for (int s = 128; s > 0; s >>= 1) {
        if (tid < s) red[tid] += red[tid + s];
        __syncthreads();
    }
    float mse = red[0] / (float)Q_ELEMS;
    __syncthreads();

    float e = 0.f;
    for (int bin = tid; bin < Kk; bin += 256) {
        float p = (float)g_hist[bin] / (float)Nn;
        e += p * logf(p + 1e-10f);
    }
    red[tid] = e;
    __syncthreads();
    for (int s = 128; s > 0; s >>= 1) {
        if (tid < s) red[tid] += red[tid + s];
        __syncthreads();
    }
    if (tid == 0 && extras) {
        out[Q_ELEMS + 0] = mse;
        out[Q_ELEMS + 1] = mse;
        out[Q_ELEMS + 2] = red[0];
    }
}

// ---------------------------------------------------------------------------
extern "C" void kernel_launch(void* const* d_in, const int* in_sizes, int n_in,
                              void* d_out, int out_size) {
    const float* x = (const float*)d_in[0];   // [32,256,32,32]
    const float* E = (const float*)d_in[1];   // [256,2048]
    float* out = (float*)d_out;
    const int extras = (out_size >= FULL_OUT) ? 1 : 0;

    k_invnorm<<<Kk / 256, 256>>>(E);
    k_prepx<<<dim3(HWp / 64, Dd / 64, Bx), 256>>>(x);
    k_prepe<<<dim3(Kk / 64, Dd / 64), 256>>>(E);

    cudaFuncSetAttribute(k_mma_argmax,
                         cudaFuncAttributeMaxDynamicSharedMemorySize, SM_TOT);
    k_mma_argmax<<<Nn / 128, 256, SM_TOT>>>();

    k_rescue<<<128, 256>>>(x);
    k_gather<<<dim3(Nn / 256, 4), 256>>>(x, E, out, extras);
    k_final<<<1, 256>>>(out, extras);
}

// round 8
// speedup vs baseline: 1.8311x; 1.2048x over previous
#include <cuda_runtime.h>
#include <cuda_bf16.h>
#include <cstdint>
#include <math.h>

#define Bx 32
#define Dd 256
#define Kk 2048
#define Nn 32768
#define HWp 1024

#define Q_ELEMS   8388608
#define FULL_OUT  8421379
#define TAU       4e-4f

// ---- device scratch (no dynamic allocations allowed) ----
__device__ __nv_bfloat16 g_Xhi[Nn * Dd];    // 16.8 MB [N][D]
__device__ __nv_bfloat16 g_Xlo[Nn * Dd];    // 16.8 MB
__device__ __nv_bfloat16 g_BhiT[Dd * Kk];   // 1 MB   [D][K]  (normalized, hi)
__device__ __nv_bfloat16 g_BloT[Dd * Kk];   // 1 MB
__device__ float g_Ef[Kk * Dd];             // 2 MB   [K][D] normalized fp32 (rescue)
__device__ float g_inv[Kk];
__device__ int   g_idx[Nn];
__device__ int   g_hist[Kk];
__device__ float g_part[512];
__device__ int   g_rcnt;
__device__ int   g_rlist[Nn];

// ======================= warp-MMA helpers (compute_80+ PTX) ================
__device__ __forceinline__ uint32_t smem_u32(const void* p) {
    uint32_t a;
    asm("{ .reg .u64 t; cvta.to.shared.u64 t, %1; cvt.u32.u64 %0, t; }" : "=r"(a) : "l"(p));
    return a;
}
__device__ __forceinline__ void ldsm_x4(uint32_t* r, uint32_t addr) {
    asm volatile("ldmatrix.sync.aligned.m8n8.x4.shared.b16 {%0,%1,%2,%3}, [%4];"
        : "=r"(r[0]), "=r"(r[1]), "=r"(r[2]), "=r"(r[3]) : "r"(addr));
}
__device__ __forceinline__ void ldsm_x4_t(uint32_t* r, uint32_t addr) {
    asm volatile("ldmatrix.sync.aligned.m8n8.x4.trans.shared.b16 {%0,%1,%2,%3}, [%4];"
        : "=r"(r[0]), "=r"(r[1]), "=r"(r[2]), "=r"(r[3]) : "r"(addr));
}
__device__ __forceinline__ void mma_bf16(float* c, const uint32_t* a, const uint32_t* b) {
    asm("mma.sync.aligned.m16n8k16.row.col.f32.bf16.bf16.f32 "
        "{%0,%1,%2,%3}, {%4,%5,%6,%7}, {%8,%9}, {%0,%1,%2,%3};"
        : "+f"(c[0]), "+f"(c[1]), "+f"(c[2]), "+f"(c[3])
        : "r"(a[0]), "r"(a[1]), "r"(a[2]), "r"(a[3]), "r"(b[0]), "r"(b[1]));
}

// ---------------------------------------------------------------------------
// Kernel 1: per-column inverse norms + zero histogram + reset rescue count
// ---------------------------------------------------------------------------
__global__ void k_invnorm(const float* __restrict__ E) {
    int k = blockIdx.x * blockDim.x + threadIdx.x;
    float ss = 0.f;
#pragma unroll 8
    for (int d = 0; d < Dd; ++d) { float v = E[d * Kk + k]; ss = fmaf(v, v, ss); }
    g_inv[k] = 1.0f / fmaxf(sqrtf(ss), 1e-12f);
    g_hist[k] = 0;
    if (k == 0) g_rcnt = 0;
}

// ---------------------------------------------------------------------------
// Kernel 2: transpose+split X: [B,D,H,W] fp32 -> Xhi/Xlo [N,D] bf16 row-major
// (paired bfloat162 stores)
// ---------------------------------------------------------------------------
__global__ __launch_bounds__(256) void k_prepx(const float* __restrict__ x) {
    __shared__ float t[64][65];
    const int tid = threadIdx.x;
    const int hw0 = blockIdx.x * 64, d0 = blockIdx.y * 64, b = blockIdx.z;
    const float* xb = x + ((size_t)b * Dd + d0) * HWp + hw0;
#pragma unroll
    for (int i = 0; i < 16; ++i) {
        int idx = i * 256 + tid, di = idx >> 6, hwi = idx & 63;
        t[di][hwi] = xb[(size_t)di * HWp + hwi];
    }
    __syncthreads();
    const int n0 = b * HWp + hw0;
#pragma unroll
    for (int i = 0; i < 8; ++i) {
        int idx = i * 256 + tid;     // 0..2047
        int hwi = idx >> 5;          // 0..63
        int di = (idx & 31) * 2;     // even d
        float v0 = t[di][hwi], v1 = t[di + 1][hwi];
        __nv_bfloat16 h0 = __float2bfloat16(v0);
        __nv_bfloat16 h1 = __float2bfloat16(v1);
        __nv_bfloat16 l0 = __float2bfloat16(v0 - __bfloat162float(h0));
        __nv_bfloat16 l1 = __float2bfloat16(v1 - __bfloat162float(h1));
        size_t o = (size_t)(n0 + hwi) * Dd + d0 + di;
        __nv_bfloat162 hh; hh.x = h0; hh.y = h1;
        __nv_bfloat162 ll; ll.x = l0; ll.y = l1;
        *reinterpret_cast<__nv_bfloat162*>(&g_Xhi[o]) = hh;
        *reinterpret_cast<__nv_bfloat162*>(&g_Xlo[o]) = ll;
    }
}

// ---------------------------------------------------------------------------
// Kernel 3: codebook prep: E [D,K] -> g_Ef [K][D] fp32 normalized,
//           g_BhiT/g_BloT [D][K] bf16 split (paired stores along K)
// ---------------------------------------------------------------------------
__global__ __launch_bounds__(256) void k_prepe(const float* __restrict__ E) {
    __shared__ float t[64][65];
    const int tid = threadIdx.x;
    const int k0 = blockIdx.x * 64, d0 = blockIdx.y * 64;
#pragma unroll
    for (int i = 0; i < 16; ++i) {
        int idx = i * 256 + tid, di = idx >> 6, ki = idx & 63;
        t[di][ki] = E[(size_t)(d0 + di) * Kk + k0 + ki] * g_inv[k0 + ki];
    }
    __syncthreads();
    // [K][D] fp32 (rescue table)
#pragma unroll
    for (int i = 0; i < 16; ++i) {
        int idx = i * 256 + tid, ki = idx >> 6, di = idx & 63;
        g_Ef[(size_t)(k0 + ki) * Dd + d0 + di] = t[di][ki];
    }
    // [D][K] bf16 hi/lo, two K at a time
#pragma unroll
    for (int i = 0; i < 8; ++i) {
        int idx = i * 256 + tid;     // 0..2047
        int di = idx >> 5;           // 0..63
        int ki = (idx & 31) * 2;     // even k
        float v0 = t[di][ki], v1 = t[di][ki + 1];
        __nv_bfloat16 h0 = __float2bfloat16(v0);
        __nv_bfloat16 h1 = __float2bfloat16(v1);
        __nv_bfloat16 l0 = __float2bfloat16(v0 - __bfloat162float(h0));
        __nv_bfloat16 l1 = __float2bfloat16(v1 - __bfloat162float(h1));
        size_t o = (size_t)(d0 + di) * Kk + k0 + ki;
        __nv_bfloat162 hh; hh.x = h0; hh.y = h1;
        __nv_bfloat162 ll; ll.x = l0; ll.y = l1;
        *reinterpret_cast<__nv_bfloat162*>(&g_BhiT[o]) = hh;
        *reinterpret_cast<__nv_bfloat162*>(&g_BloT[o]) = ll;
    }
}

// ---------------------------------------------------------------------------
// Kernel 4: warp-MMA split-3 bf16 GEMM + top-2 argmax.
// CTA: 256 thr / 64 rows (A hi+lo resident, 64KB). 8 warps: wm=wid&1 (32-row
// group), wn=wid>>1 (32-col group). B streamed as [k32][n128] double-buffered
// stages (16KB each). 2 CTAs/SM target; 128 syncs per CTA.
// ---------------------------------------------------------------------------
#define SM_ALO 32768
#define SM_B   65536
#define SM_RED 98304
#define SM_TOT 101376

__global__ __launch_bounds__(256, 2) void k_mma_argmax() {
    extern __shared__ char sm[];
    const uint32_t sb = smem_u32(sm);
    const int tid = threadIdx.x;
    const int lane = tid & 31;
    const int wid = tid >> 5;
    const int wm = wid & 1, wn = wid >> 1;
    const int rbase = blockIdx.x * 64;

    // ---- load A (both splits) into swizzled SMEM: row stride 512B ----
#pragma unroll
    for (int s = 0; s < 2; ++s) {
        const __nv_bfloat16* src = s ? g_Xlo : g_Xhi;
#pragma unroll
        for (int i = 0; i < 8; ++i) {
            int idx = i * 256 + tid;       // 2048 uint4
            int r = idx >> 5, u = idx & 31;
            uint4 v = *(const uint4*)(src + (size_t)(rbase + r) * Dd + u * 8);
            *(uint4*)(sm + s * SM_ALO + r * 512 + ((u ^ (r & 7)) << 4)) = v;
        }
    }
    // ---- preload B chunk 0 (ct=0,kc=0) into stage 0 ----
#pragma unroll
    for (int j = 0; j < 2; ++j) {
        int idx = j * 256 + tid;           // 512 uint4 per split
        int r = idx >> 4, u = idx & 15;
        const char* sh = (const char*)g_BhiT + ((size_t)r * Kk) * 2 + u * 16;
        const char* sl = (const char*)g_BloT + ((size_t)r * Kk) * 2 + u * 16;
        uint32_t dst = SM_B + r * 256 + ((u ^ (r & 7)) << 4);
        *(uint4*)(sm + dst) = *(const uint4*)sh;
        *(uint4*)(sm + dst + 8192) = *(const uint4*)sl;
    }
    __syncthreads();

    float c[2][4][4];
#pragma unroll
    for (int mi = 0; mi < 2; ++mi)
#pragma unroll
        for (int j = 0; j < 4; ++j)
#pragma unroll
            for (int q = 0; q < 4; ++q) c[mi][j][q] = 0.f;

    float v1[4], v2[4];
    int   i1[4];
#pragma unroll
    for (int s = 0; s < 4; ++s) { v1[s] = -3.0e38f; v2[s] = -3.0e38f; i1[s] = 0; }

    int stage = 0;
    uint4 nh[2], nl[2];
    const int ldr = tid >> 4, ldu = tid & 15;
    const int kk = (lane & 7) + ((lane >> 3) & 1) * 8;

    for (int cid = 0; cid < 128; ++cid) {
        const int ct = cid >> 3, kc = cid & 7;

        // prefetch next chunk (LDG only; STS after MMA)
        if (cid < 127) {
            int nct = (cid + 1) >> 3, nkc = (cid + 1) & 7;
            size_t so = ((size_t)(nkc * 32 + ldr) * Kk + nct * 128) * 2 + (size_t)ldu * 16;
#pragma unroll
            for (int j = 0; j < 2; ++j) {
                nh[j] = *(const uint4*)((const char*)g_BhiT + so + (size_t)j * 16 * Kk * 2);
                nl[j] = *(const uint4*)((const char*)g_BloT + so + (size_t)j * 16 * Kk * 2);
            }
        }

        // ---- two k16 sub-chunks ----
#pragma unroll
        for (int kcs = 0; kcs < 2; ++kcs) {
            uint32_t ah[2][4], al[2][4];
#pragma unroll
            for (int mi = 0; mi < 2; ++mi) {
                int r0 = wm * 32 + mi * 16 + (lane & 15);
                int u0 = kc * 4 + kcs * 2 + (lane >> 4);
                uint32_t aaddr = sb + r0 * 512 + ((u0 ^ (r0 & 7)) << 4);
                ldsm_x4(ah[mi], aaddr);
                ldsm_x4(al[mi], aaddr + SM_ALO);
            }
            uint32_t bh[2][4], bl[2][4];
            const uint32_t bbase = sb + SM_B + stage * 16384 + kcs * 4096;
#pragma unroll
            for (int p = 0; p < 2; ++p) {
                int u0 = wn * 4 + p * 2 + (lane >> 4);
                uint32_t baddr = bbase + kk * 256 + ((u0 ^ (kk & 7)) << 4);
                ldsm_x4_t(bh[p], baddr);
                ldsm_x4_t(bl[p], baddr + 8192);
            }
            // ---- 24 HMMA: hi*hi + hi*lo + lo*hi ----
#pragma unroll
            for (int mi = 0; mi < 2; ++mi)
#pragma unroll
                for (int p = 0; p < 2; ++p) {
                    mma_bf16(c[mi][2 * p],     ah[mi], &bh[p][0]);
                    mma_bf16(c[mi][2 * p + 1], ah[mi], &bh[p][2]);
                    mma_bf16(c[mi][2 * p],     ah[mi], &bl[p][0]);
                    mma_bf16(c[mi][2 * p + 1], ah[mi], &bl[p][2]);
                    mma_bf16(c[mi][2 * p],     al[mi], &bh[p][0]);
                    mma_bf16(c[mi][2 * p + 1], al[mi], &bh[p][2]);
                }
        }

        // store prefetched chunk into other stage
        if (cid < 127) {
            uint32_t dst = SM_B + (stage ^ 1) * 16384 + ldr * 256 + ((ldu ^ (ldr & 7)) << 4);
#pragma unroll
            for (int j = 0; j < 2; ++j) {
                *(uint4*)(sm + dst + j * 4096) = nh[j];
                *(uint4*)(sm + dst + j * 4096 + 8192) = nl[j];
            }
        }
        __syncthreads();
        stage ^= 1;

        // ---- column-tile epilogue: fold accumulators into running top-2 ----
        if (kc == 7) {
            const int cb = ct * 128 + wn * 32 + (lane & 3) * 2;
#pragma unroll
            for (int mi = 0; mi < 2; ++mi)
#pragma unroll
                for (int j = 0; j < 4; ++j)
#pragma unroll
                    for (int q = 0; q < 4; ++q) {
                        float v = c[mi][j][q];
                        int col = cb + j * 8 + (q & 1);
                        int slot = mi * 2 + (q >> 1);
                        if (v > v1[slot]) { v2[slot] = v1[slot]; v1[slot] = v; i1[slot] = col; }
                        else if (v > v2[slot]) { v2[slot] = v; }
                        c[mi][j][q] = 0.f;
                    }
        }
    }

    // ---- cross-lane merge over the 4 lanes sharing a row ----
#pragma unroll
    for (int s = 0; s < 4; ++s) {
#pragma unroll
        for (int m = 1; m <= 2; m <<= 1) {
            float ov1 = __shfl_xor_sync(0xffffffffu, v1[s], m);
            float ov2 = __shfl_xor_sync(0xffffffffu, v2[s], m);
            int   oi1 = __shfl_xor_sync(0xffffffffu, i1[s], m);
            if (ov1 > v1[s]) { v2[s] = fmaxf(v1[s], ov2); v1[s] = ov1; i1[s] = oi1; }
            else             { v2[s] = fmaxf(v2[s], ov1); }
        }
    }
    float* sv1 = (float*)(sm + SM_RED);
    float* sv2 = (float*)(sm + SM_RED + 1024);
    int*   si1 = (int*)  (sm + SM_RED + 2048);
    if ((lane & 3) == 0) {
#pragma unroll
        for (int s = 0; s < 4; ++s) {
            int row = wm * 32 + (s >> 1) * 16 + (s & 1) * 8 + (lane >> 2);
            sv1[row * 4 + wn] = v1[s];
            sv2[row * 4 + wn] = v2[s];
            si1[row * 4 + wn] = i1[s];
        }
    }
    __syncthreads();
    if (tid < 64) {
        float t1 = -3.0e38f, t2 = -3.0e38f;
        int ti = 0;
#pragma unroll
        for (int p = 0; p < 4; ++p) {
            float a1 = sv1[tid * 4 + p], a2 = sv2[tid * 4 + p];
            int ai = si1[tid * 4 + p];
            if (a1 > t1) { t2 = fmaxf(t1, a2); t1 = a1; ti = ai; }
            else         { t2 = fmaxf(t2, a1); }
        }
        g_idx[rbase + tid] = ti;
        if (t1 - t2 < TAU) {
            int p = atomicAdd(&g_rcnt, 1);
            g_rlist[p] = rbase + tid;
        }
    }
}

// ---------------------------------------------------------------------------
// Kernel 5: exact fp32 rescue for rows with small top1-top2 gap.
// ---------------------------------------------------------------------------
__global__ __launch_bounds__(256) void k_rescue(const float* __restrict__ x) {
    __shared__ float sx[8][257];
    __shared__ int   srows[8];
    __shared__ float rv[256];
    __shared__ int   ri[256];
    const int tid = threadIdx.x;
    const int total = g_rcnt;

    for (int t0 = blockIdx.x * 8; t0 < total; t0 += gridDim.x * 8) {
        const int m = min(8, total - t0);
        if (tid < 8) srows[tid] = (tid < m) ? g_rlist[t0 + tid] : 0;
        __syncthreads();
        for (int j = 0; j < 8; ++j) {
            int n = srows[j];
            int b = n >> 10, hw = n & 1023;
            sx[j][tid] = (j < m) ? x[((size_t)b * Dd + tid) * HWp + hw] : 0.f;
        }
        __syncthreads();

        float bv[8]; int bi[8];
#pragma unroll
        for (int j = 0; j < 8; ++j) { bv[j] = -3.0e38f; bi[j] = 0; }
        for (int s = 0; s < 8; ++s) {
            int k = s * 256 + tid;
            const float* er = g_Ef + (size_t)k * Dd;
            float dot[8];
#pragma unroll
            for (int j = 0; j < 8; ++j) dot[j] = 0.f;
            for (int d = 0; d < Dd; d += 4) {
                float4 e = *(const float4*)(er + d);
#pragma unroll
                for (int j = 0; j < 8; ++j) {
                    dot[j] = fmaf(sx[j][d], e.x, dot[j]);
                    dot[j] = fmaf(sx[j][d + 1], e.y, dot[j]);
                    dot[j] = fmaf(sx[j][d + 2], e.z, dot[j]);
                    dot[j] = fmaf(sx[j][d + 3], e.w, dot[j]);
                }
            }
#pragma unroll
            for (int j = 0; j < 8; ++j)
                if (dot[j] > bv[j]) { bv[j] = dot[j]; bi[j] = k; }
        }
        for (int j = 0; j < 8; ++j) {
            rv[tid] = bv[j]; ri[tid] = bi[j];
            __syncthreads();
            for (int s2 = 128; s2 > 0; s2 >>= 1) {
                if (tid < s2) {
                    if (rv[tid + s2] > rv[tid] ||
                        (rv[tid + s2] == rv[tid] && ri[tid + s2] < ri[tid])) {
                        rv[tid] = rv[tid + s2]; ri[tid] = ri[tid + s2];
                    }
                }
                __syncthreads();
            }
            if (tid == 0 && j < m) g_idx[srows[j]] = ri[0];
            __syncthreads();
        }
    }
}

// ---------------------------------------------------------------------------
// Kernel 6: gather + fused MSE partials + histogram + index output.
// ---------------------------------------------------------------------------
__global__ void k_gather(const float* __restrict__ x, const float* __restrict__ E,
                         float* __restrict__ out, int extras) {
    __shared__ float red[256];
    const int tid = threadIdx.x;
    const int n = blockIdx.x * 256 + tid;
    const int q = blockIdx.y;
    const int d0 = q * 64;
    const int idx = g_idx[n];
    const int b = n >> 10;
    const int hw = n & 1023;

    const float* xb = x + ((size_t)b * Dd + d0) * HWp + hw;
    float* ob = out + ((size_t)b * Dd + d0) * HWp + hw;

    float acc = 0.f;
#pragma unroll 4
    for (int d = 0; d < 64; ++d) {
        float qv = E[(d0 + d) * Kk + idx];
        float xv = xb[(size_t)d * HWp];
        ob[(size_t)d * HWp] = qv;
        float df = xv - qv;
        acc = fmaf(df, df, acc);
    }
    if (q == 0) {
        atomicAdd(&g_hist[idx], 1);
        if (extras) out[Q_ELEMS + 3 + n] = (float)idx;
    }

    red[tid] = acc;
    __syncthreads();
    for (int s = 128; s > 0; s >>= 1) {
        if (tid < s) red[tid] += red[tid + s];
        __syncthreads();
    }
    if (tid == 0) g_part[blockIdx.x * 4 + q] = red[0];
}

// ---------------------------------------------------------------------------
// Kernel 7: finalize scalars
// ---------------------------------------------------------------------------
__global__ void k_final(float* __restrict__ out, int extras) {
    __shared__ float red[256];
    const int tid = threadIdx.x;

    red[tid] = g_part[tid] + g_part[tid + 256];
    __syncthreads();
    for (int s = 128; s > 0; s >>= 1) {
        if (tid < s) red[tid] += red[tid + s];
        __syncthreads();
    }
    float mse = red[0] / (float)Q_ELEMS;
    __syncthreads();

    float e = 0.f;
    for (int bin = tid; bin < Kk; bin += 256) {
        float p = (float)g_hist[bin] / (float)Nn;
        e += p * logf(p + 1e-10f);
    }
    red[tid] = e;
    __syncthreads();
    for (int s = 128; s > 0; s >>= 1) {
        if (tid < s) red[tid] += red[tid + s];
        __syncthreads();
    }
    if (tid == 0 && extras) {
        out[Q_ELEMS + 0] = mse;
        out[Q_ELEMS + 1] = mse;
        out[Q_ELEMS + 2] = red[0];
    }
}

// ---------------------------------------------------------------------------
extern "C" void kernel_launch(void* const* d_in, const int* in_sizes, int n_in,
                              void* d_out, int out_size) {
    const float* x = (const float*)d_in[0];   // [32,256,32,32]
    const float* E = (const float*)d_in[1];   // [256,2048]
    float* out = (float*)d_out;
    const int extras = (out_size >= FULL_OUT) ? 1 : 0;

    k_invnorm<<<Kk / 256, 256>>>(E);
    k_prepx<<<dim3(HWp / 64, Dd / 64, Bx), 256>>>(x);
    k_prepe<<<dim3(Kk / 64, Dd / 64), 256>>>(E);

    cudaFuncSetAttribute(k_mma_argmax,
                         cudaFuncAttributeMaxDynamicSharedMemorySize, SM_TOT);
    k_mma_argmax<<<Nn / 64, 256, SM_TOT>>>();

    k_rescue<<<128, 256>>>(x);
    k_gather<<<dim3(Nn / 256, 4), 256>>>(x, E, out, extras);
    k_final<<<1, 256>>>(out, extras);
}